// round 12
// baseline (speedup 1.0000x reference)
#include <cuda_runtime.h>
#include <cuda_bf16.h>

// loss = sum_{b,c,s,h,w} (out[b,c,2s,h,w] - target[b,c,2s+1,h,w])^2 / (C*H*Wd * W/2)
// B=8, C=32, W=16 (s=0..7), H=128, Wd=128.
//
// 2048 slabs (g = flattened b,c,s). Slab g:
//   out float4 base : out4 + (g<<13)          (4096 float4 = 64 KB)
//   tgt float4 base : tgt4 + (g<<13) + 4096   (4096 float4 = 64 KB)
//
// Completion protocol (fence-free, integer-exact), now STRIPED:
//   32 packed u64 slots, 256 B apart (distinct LTS slices). CTA i fires one
//   red.add.relaxed.gpu.u64 of (fixed_sum + 1<<44) into slot i&31. Per-slot
//   sum+count travel in the same 8-byte word, so no cross-address ordering is
//   needed. Spinner (CTA 2047) polls all slots until total count = 2048,
//   then scales, writes d_out, and re-arms all slots for graph replay.
//   Integer accumulation -> bit-exact, deterministic (rel_err 0).

#define NBLOCKS 2048
#define NTHREADS 256
#define PER_THREAD 16   // 4096 / 256

#define NSLOTS 32
#define SLOT_STRIDE 32           // u64s per slot stride = 256 bytes
#define COUNT_SHIFT 44
#define SUM_MASK ((1ULL << COUNT_SHIFT) - 1ULL)
#define FIX_SCALE 4096.0         // 2^12

__device__ unsigned long long g_slots[NSLOTS * SLOT_STRIDE];  // zero-init; re-armed each launch

__global__ __launch_bounds__(NTHREADS) void cont_loss_kernel(
    const float4* __restrict__ out4, const float4* __restrict__ tgt4,
    float* __restrict__ result)
{
    const long long base = ((long long)blockIdx.x << 13);
    const float4* __restrict__ op = out4 + base + threadIdx.x;
    const float4* __restrict__ tp = tgt4 + base + 4096 + threadIdx.x;

    float a0 = 0.0f, a1 = 0.0f, a2 = 0.0f, a3 = 0.0f;
    #pragma unroll
    for (int k = 0; k < PER_THREAD; k++) {
        float4 o = op[k * NTHREADS];
        float4 t = tp[k * NTHREADS];
        float d0 = o.x - t.x;
        float d1 = o.y - t.y;
        float d2 = o.z - t.z;
        float d3 = o.w - t.w;
        a0 = fmaf(d0, d0, a0);
        a1 = fmaf(d1, d1, a1);
        a2 = fmaf(d2, d2, a2);
        a3 = fmaf(d3, d3, a3);
    }
    float acc = (a0 + a1) + (a2 + a3);

    // deterministic in-block smem tree
    __shared__ float sbuf[NTHREADS];
    sbuf[threadIdx.x] = acc;
    __syncthreads();
    #pragma unroll
    for (int ofs = NTHREADS / 2; ofs > 0; ofs >>= 1) {
        if (threadIdx.x < ofs) sbuf[threadIdx.x] += sbuf[threadIdx.x + ofs];
        __syncthreads();
    }

    if (threadIdx.x == 0) {
        unsigned long long fixed =
            (unsigned long long)__double2ll_rn((double)sbuf[0] * FIX_SCALE);
        unsigned long long pkt = fixed + (1ULL << COUNT_SHIFT);
        unsigned long long* slot =
            &g_slots[(blockIdx.x & (NSLOTS - 1)) * SLOT_STRIDE];
        asm volatile("red.add.relaxed.gpu.u64 [%0], %1;"
                     :: "l"(slot), "l"(pkt) : "memory");

        // Spinner: poll all 32 slots until every CTA has arrived.
        if (blockIdx.x == NBLOCKS - 1) {
            unsigned long long v[NSLOTS];
            for (;;) {
                unsigned long long cnt = 0;
                #pragma unroll
                for (int s = 0; s < NSLOTS; s++) {
                    asm volatile("ld.relaxed.gpu.u64 %0, [%1];"
                                 : "=l"(v[s]) : "l"(&g_slots[s * SLOT_STRIDE]));
                    cnt += v[s] >> COUNT_SHIFT;
                }
                if (cnt >= (unsigned long long)NBLOCKS) break;
                __nanosleep(100);
            }

            unsigned long long isum = 0;
            #pragma unroll
            for (int s = 0; s < NSLOTS; s++) isum += v[s] & SUM_MASK;

            double total = (double)(long long)isum / FIX_SCALE;
            const double scale = 1.0 / (524288.0 * 8.0);  // 2^-22, exact
            result[0] = (float)(total * scale);

            // re-arm all slots for next graph replay
            #pragma unroll
            for (int s = 0; s < NSLOTS; s++)
                asm volatile("st.relaxed.gpu.u64 [%0], %1;"
                             :: "l"(&g_slots[s * SLOT_STRIDE]), "l"(0ULL) : "memory");
        }
    }
}

extern "C" void kernel_launch(void* const* d_in, const int* in_sizes, int n_in,
                              void* d_out, int out_size)
{
    const float4* out4 = (const float4*)d_in[0];
    const float4* tgt4 = (const float4*)d_in[1];
    float* o = (float*)d_out;

    cont_loss_kernel<<<NBLOCKS, NTHREADS>>>(out4, tgt4, o);
}

// round 13
// speedup vs baseline: 1.0051x; 1.0051x over previous
#include <cuda_runtime.h>
#include <cuda_bf16.h>

// loss = sum_{b,c,s,h,w} (out[b,c,2s,h,w] - target[b,c,2s+1,h,w])^2 / (C*H*Wd * W/2)
// B=8, C=32, W=16 (s=0..7), H=128, Wd=128.
//
// 2048 slabs (g = flattened b,c,s). Slab g (in floats):
//   out base : (g<<15)           16384 floats
//   tgt base : (g<<15) + 16384   16384 floats
//
// Mainloop: 256-bit loads (ld.global.nc.v8.f32, sm_100+) -> half the LSU ops,
// 2x bytes in flight per instruction vs LDG.128.
//
// Completion protocol (proven best, R11): ONE red.add.relaxed.gpu.u64 per CTA
// into a packed word (low 44 bits: fixed-point sum * 2^12; high bits: count).
// Sum+count share one 8-byte word -> no cross-address ordering, no fences.
// Spinner (CTA 2047) polls, scales by exact 2^-22 / 2^12, writes d_out,
// re-arms the word. Integer accumulation -> deterministic, rel_err 0.

#define NBLOCKS 2048
#define NTHREADS 256
#define V8_PER_THREAD 8        // 2048 v8-chunks per slab / 256 threads
#define V8_STRIDE 2048         // floats between consecutive k for one thread

#define COUNT_SHIFT 44
#define SUM_MASK ((1ULL << COUNT_SHIFT) - 1ULL)
#define FIX_SCALE 4096.0       // 2^12

__device__ unsigned long long g_packed = 0ULL;  // re-armed by spinner each launch

__global__ __launch_bounds__(NTHREADS) void cont_loss_kernel(
    const float* __restrict__ outf, const float* __restrict__ tgtf,
    float* __restrict__ result)
{
    const long long base = ((long long)blockIdx.x << 15);
    const float* op = outf + base + (threadIdx.x << 3);
    const float* tp = tgtf + base + 16384 + (threadIdx.x << 3);

    float a0 = 0.0f, a1 = 0.0f, a2 = 0.0f, a3 = 0.0f;
    #pragma unroll
    for (int k = 0; k < V8_PER_THREAD; k++) {
        float o0,o1,o2,o3,o4,o5,o6,o7;
        float t0,t1,t2,t3,t4,t5,t6,t7;
        asm("ld.global.nc.v8.f32 {%0,%1,%2,%3,%4,%5,%6,%7}, [%8];"
            : "=f"(o0),"=f"(o1),"=f"(o2),"=f"(o3),
              "=f"(o4),"=f"(o5),"=f"(o6),"=f"(o7)
            : "l"(op + k * V8_STRIDE));
        asm("ld.global.nc.v8.f32 {%0,%1,%2,%3,%4,%5,%6,%7}, [%8];"
            : "=f"(t0),"=f"(t1),"=f"(t2),"=f"(t3),
              "=f"(t4),"=f"(t5),"=f"(t6),"=f"(t7)
            : "l"(tp + k * V8_STRIDE));
        float d0 = o0 - t0, d1 = o1 - t1, d2 = o2 - t2, d3 = o3 - t3;
        float d4 = o4 - t4, d5 = o5 - t5, d6 = o6 - t6, d7 = o7 - t7;
        a0 = fmaf(d0, d0, a0);
        a1 = fmaf(d1, d1, a1);
        a2 = fmaf(d2, d2, a2);
        a3 = fmaf(d3, d3, a3);
        a0 = fmaf(d4, d4, a0);
        a1 = fmaf(d5, d5, a1);
        a2 = fmaf(d6, d6, a2);
        a3 = fmaf(d7, d7, a3);
    }
    float acc = (a0 + a1) + (a2 + a3);

    // deterministic in-block smem tree
    __shared__ float sbuf[NTHREADS];
    sbuf[threadIdx.x] = acc;
    __syncthreads();
    #pragma unroll
    for (int ofs = NTHREADS / 2; ofs > 0; ofs >>= 1) {
        if (threadIdx.x < ofs) sbuf[threadIdx.x] += sbuf[threadIdx.x + ofs];
        __syncthreads();
    }

    if (threadIdx.x == 0) {
        unsigned long long fixed =
            (unsigned long long)__double2ll_rn((double)sbuf[0] * FIX_SCALE);
        unsigned long long pkt = fixed + (1ULL << COUNT_SHIFT);
        asm volatile("red.add.relaxed.gpu.u64 [%0], %1;"
                     :: "l"(&g_packed), "l"(pkt) : "memory");

        // Spinner: same-address polling, no fences (sum+count in one word).
        if (blockIdx.x == NBLOCKS - 1) {
            unsigned long long v;
            do {
                __nanosleep(100);
                asm volatile("ld.relaxed.gpu.u64 %0, [%1];"
                             : "=l"(v) : "l"(&g_packed));
            } while ((v >> COUNT_SHIFT) < (unsigned long long)NBLOCKS);

            double total = (double)(long long)(v & SUM_MASK) / FIX_SCALE;
            const double scale = 1.0 / (524288.0 * 8.0);  // 2^-22, exact
            result[0] = (float)(total * scale);

            asm volatile("st.relaxed.gpu.u64 [%0], %1;"
                         :: "l"(&g_packed), "l"(0ULL) : "memory");
        }
    }
}

extern "C" void kernel_launch(void* const* d_in, const int* in_sizes, int n_in,
                              void* d_out, int out_size)
{
    const float* outf = (const float*)d_in[0];
    const float* tgtf = (const float*)d_in[1];
    float* o = (float*)d_out;

    cont_loss_kernel<<<NBLOCKS, NTHREADS>>>(outf, tgtf, o);
}

// round 14
// speedup vs baseline: 1.0111x; 1.0059x over previous
#include <cuda_runtime.h>
#include <cuda_bf16.h>

// loss = sum_{b,c,s,h,w} (out[b,c,2s,h,w] - target[b,c,2s+1,h,w])^2 / (C*H*Wd * W/2)
// B=8, C=32, W=16 (s=0..7), H=128, Wd=128.
//
// 2048 slabs (g = flattened b,c,s). Slab g:
//   out float4 base : out4 + (g<<13)          (4096 float4 = 64 KB)
//   tgt float4 base : tgt4 + (g<<13) + 4096   (4096 float4 = 64 KB)
//
// Completion protocol (no spinner, no memset, no fences):
//   ONE atom.add.relaxed.gpu.u64 WITH RETURN per CTA into a packed word
//   (low 44 bits: fixed-point sum * 2^12; high bits: arrival count).
//   Sum and count share one 8-byte word, so the CTA whose returned count is
//   NBLOCKS-1 holds the COMPLETE final sum = old.sum + own contribution.
//   It writes d_out and re-arms the word for the next graph replay.
//   Integer accumulation -> bit-exact, deterministic (rel_err 0).

#define NBLOCKS 2048
#define NTHREADS 256
#define PER_THREAD 16   // 4096 / 256

#define COUNT_SHIFT 44
#define SUM_MASK ((1ULL << COUNT_SHIFT) - 1ULL)
#define FIX_SCALE 4096.0   // 2^12

__device__ unsigned long long g_packed = 0ULL;  // re-armed by finisher each launch

__global__ __launch_bounds__(NTHREADS) void cont_loss_kernel(
    const float4* __restrict__ out4, const float4* __restrict__ tgt4,
    float* __restrict__ result)
{
    const long long base = ((long long)blockIdx.x << 13);
    const float4* __restrict__ op = out4 + base + threadIdx.x;
    const float4* __restrict__ tp = tgt4 + base + 4096 + threadIdx.x;

    float a0 = 0.0f, a1 = 0.0f, a2 = 0.0f, a3 = 0.0f;
    #pragma unroll
    for (int k = 0; k < PER_THREAD; k++) {
        float4 o = op[k * NTHREADS];
        float4 t = tp[k * NTHREADS];
        float d0 = o.x - t.x;
        float d1 = o.y - t.y;
        float d2 = o.z - t.z;
        float d3 = o.w - t.w;
        a0 = fmaf(d0, d0, a0);
        a1 = fmaf(d1, d1, a1);
        a2 = fmaf(d2, d2, a2);
        a3 = fmaf(d3, d3, a3);
    }
    float acc = (a0 + a1) + (a2 + a3);

    // warp shuffle tree + cross-warp via smem (single __syncthreads)
    #pragma unroll
    for (int ofs = 16; ofs > 0; ofs >>= 1)
        acc += __shfl_down_sync(0xFFFFFFFFu, acc, ofs);

    __shared__ float swarp[NTHREADS / 32];
    const int lane = threadIdx.x & 31;
    const int wid  = threadIdx.x >> 5;
    if (lane == 0) swarp[wid] = acc;
    __syncthreads();

    if (threadIdx.x == 0) {
        float blk = 0.0f;
        #pragma unroll
        for (int w = 0; w < NTHREADS / 32; w++) blk += swarp[w];

        unsigned long long fixed =
            (unsigned long long)__double2ll_rn((double)blk * FIX_SCALE);
        unsigned long long pkt = fixed + (1ULL << COUNT_SHIFT);

        unsigned long long old;
        asm volatile("atom.add.relaxed.gpu.u64 %0, [%1], %2;"
                     : "=l"(old) : "l"(&g_packed), "l"(pkt) : "memory");

        // Last arrival holds the complete sum in (old + own contribution).
        if ((old >> COUNT_SHIFT) == (unsigned long long)(NBLOCKS - 1)) {
            unsigned long long isum = (old & SUM_MASK) + fixed;
            double total = (double)(long long)isum / FIX_SCALE;
            const double scale = 1.0 / (524288.0 * 8.0);  // 2^-22, exact
            result[0] = (float)(total * scale);

            // re-arm for next graph replay (everyone has already added)
            asm volatile("st.relaxed.gpu.u64 [%0], %1;"
                         :: "l"(&g_packed), "l"(0ULL) : "memory");
        }
    }
}

extern "C" void kernel_launch(void* const* d_in, const int* in_sizes, int n_in,
                              void* d_out, int out_size)
{
    const float4* out4 = (const float4*)d_in[0];
    const float4* tgt4 = (const float4*)d_in[1];
    float* o = (float*)d_out;

    cont_loss_kernel<<<NBLOCKS, NTHREADS>>>(out4, tgt4, o);
}

// round 15
// speedup vs baseline: 1.0217x; 1.0105x over previous
#include <cuda_runtime.h>
#include <cuda_bf16.h>

// loss = sum_{b,c,s,h,w} (out[b,c,2s,h,w] - target[b,c,2s+1,h,w])^2 / (C*H*Wd * W/2)
// B=8, C=32, W=16 (s=0..7), H=128, Wd=128.
//
// 2048 slabs (g = flattened b,c,s). Slab g:
//   out float4 base : out4 + (g<<13)          (4096 float4 = 64 KB)
//   tgt float4 base : tgt4 + (g<<13) + 4096   (4096 float4 = 64 KB)
//
// Minimal completion structure: d_out IS the accumulator.
//   - CTA 0 / thread 0, first instructions: old = d_out; red.add(d_out, -old)
//     -> exactly cancels the previous replay's value (graph replays serialize,
//     and no CTA can finish 128 KB of streaming before CTA0 issues 2 instrs;
//     safety margin ~10x in cycles).
//   - Every CTA fire-and-forgets ONE red.add.relaxed.gpu.f32 of its partial,
//     pre-scaled by the EXACT power-of-two 2^-22, then retires immediately.
// No memset node, no counter, no finisher, no fences, no return-atomics.

#define NBLOCKS 2048
#define NTHREADS 256
#define PER_THREAD 16   // 4096 / 256

__global__ __launch_bounds__(NTHREADS) void cont_loss_kernel(
    const float4* __restrict__ out4, const float4* __restrict__ tgt4,
    float* __restrict__ result)
{
    // Self-canceling reset of the accumulator (previous replay's value).
    if (blockIdx.x == 0 && threadIdx.x == 0) {
        float old;
        asm volatile("ld.relaxed.gpu.f32 %0, [%1];"
                     : "=f"(old) : "l"(result) : "memory");
        asm volatile("red.add.relaxed.gpu.f32 [%0], %1;"
                     :: "l"(result), "f"(-old) : "memory");
    }

    const long long base = ((long long)blockIdx.x << 13);
    const float4* __restrict__ op = out4 + base + threadIdx.x;
    const float4* __restrict__ tp = tgt4 + base + 4096 + threadIdx.x;

    float a0 = 0.0f, a1 = 0.0f, a2 = 0.0f, a3 = 0.0f;
    #pragma unroll
    for (int k = 0; k < PER_THREAD; k++) {
        float4 o = op[k * NTHREADS];
        float4 t = tp[k * NTHREADS];
        float d0 = o.x - t.x;
        float d1 = o.y - t.y;
        float d2 = o.z - t.z;
        float d3 = o.w - t.w;
        a0 = fmaf(d0, d0, a0);
        a1 = fmaf(d1, d1, a1);
        a2 = fmaf(d2, d2, a2);
        a3 = fmaf(d3, d3, a3);
    }
    float acc = (a0 + a1) + (a2 + a3);

    // deterministic in-block smem tree (R9's exact tail shape)
    __shared__ float sbuf[NTHREADS];
    sbuf[threadIdx.x] = acc;
    __syncthreads();
    #pragma unroll
    for (int ofs = NTHREADS / 2; ofs > 0; ofs >>= 1) {
        if (threadIdx.x < ofs) sbuf[threadIdx.x] += sbuf[threadIdx.x + ofs];
        __syncthreads();
    }

    if (threadIdx.x == 0) {
        // 2^-22: exact scaling (exponent shift only)
        float scaled = sbuf[0] * 2.384185791015625e-07f;
        asm volatile("red.add.relaxed.gpu.f32 [%0], %1;"
                     :: "l"(result), "f"(scaled) : "memory");
    }
}

extern "C" void kernel_launch(void* const* d_in, const int* in_sizes, int n_in,
                              void* d_out, int out_size)
{
    const float4* out4 = (const float4*)d_in[0];
    const float4* tgt4 = (const float4*)d_in[1];
    float* o = (float*)d_out;

    cont_loss_kernel<<<NBLOCKS, NTHREADS>>>(out4, tgt4, o);
}